// round 3
// baseline (speedup 1.0000x reference)
#include <cuda_runtime.h>
#include <math.h>

#define BB 4
#define NN 2048
#define DIM 768
#define NH 12
#define HD 64
#define MROWS (BB*NN)   // 8192

// Scratch: q,k,v in [b,h,n,d] layout (25.2 MB each)
__device__ float g_q[BB*NH*NN*HD];
__device__ float g_k[BB*NH*NN*HD];
__device__ float g_v[BB*NH*NN*HD];

// =====================  QKV projection GEMM  =====================
// y[m][o] = sum_k x[m][k] * W[o][k] + bias[o]   (torch Linear: x @ W.T + b)
// Written head-split into g_q/g_k/g_v.
#define Bb_M 128
#define Bb_N 128
#define KC   16
#define XPAD 132   // 128 + 4 pad, 528B rows (16B multiple)

__global__ __launch_bounds__(256) void qkv_kernel(
    const float* __restrict__ x,
    const float* __restrict__ wq, const float* __restrict__ bq,
    const float* __restrict__ wk, const float* __restrict__ bk,
    const float* __restrict__ wv, const float* __restrict__ bv)
{
    __shared__ float Xs[KC][XPAD];   // [k][m-row]
    __shared__ float Ws[KC][XPAD];   // [k][o-row]

    const int mat = blockIdx.z;
    const float* w    = (mat == 0) ? wq : (mat == 1) ? wk : wv;
    const float* bias = (mat == 0) ? bq : (mat == 1) ? bk : bv;
    float* dst        = (mat == 0) ? g_q : (mat == 1) ? g_k : g_v;

    const int m0 = blockIdx.y * Bb_M;
    const int o0 = blockIdx.x * Bb_N;
    const int tid = threadIdx.x;
    const int ty = tid >> 4, tx = tid & 15;

    float acc[8][8];
#pragma unroll
    for (int i = 0; i < 8; i++)
#pragma unroll
        for (int j = 0; j < 8; j++) acc[i][j] = 0.f;

    for (int kb = 0; kb < DIM; kb += KC) {
        __syncthreads();
        // 128 rows x 16 k = 512 float4 per operand; 2 per thread
#pragma unroll
        for (int p = 0; p < 2; p++) {
            int idx = tid + p * 256;
            int row = idx >> 2;       // 0..127
            int k4  = idx & 3;        // float4 index within 16-wide k chunk
            float4 xv = *(const float4*)(x + (size_t)(m0 + row) * DIM + kb + 4 * k4);
            float4 wv4 = *(const float4*)(w + (size_t)(o0 + row) * DIM + kb + 4 * k4);
            Xs[4*k4+0][row] = xv.x;  Xs[4*k4+1][row] = xv.y;
            Xs[4*k4+2][row] = xv.z;  Xs[4*k4+3][row] = xv.w;
            Ws[4*k4+0][row] = wv4.x; Ws[4*k4+1][row] = wv4.y;
            Ws[4*k4+2][row] = wv4.z; Ws[4*k4+3][row] = wv4.w;
        }
        __syncthreads();
#pragma unroll
        for (int kk = 0; kk < KC; kk++) {
            float a[8], bv[8];
            *(float4*)(a)     = *(const float4*)&Xs[kk][8*ty];
            *(float4*)(a + 4) = *(const float4*)&Xs[kk][8*ty + 4];
            *(float4*)(bv)    = *(const float4*)&Ws[kk][8*tx];
            *(float4*)(bv + 4)= *(const float4*)&Ws[kk][8*tx + 4];
#pragma unroll
            for (int i = 0; i < 8; i++)
#pragma unroll
                for (int j = 0; j < 8; j++)
                    acc[i][j] = fmaf(a[i], bv[j], acc[i][j]);
        }
    }

    // Write out with bias, head-split layout [b,h,n,d]
#pragma unroll
    for (int i = 0; i < 8; i++) {
        int m = m0 + 8 * ty + i;
        int b_ = m / NN, n = m % NN;
#pragma unroll
        for (int j = 0; j < 8; j++) {
            int o = o0 + 8 * tx + j;
            int h = o / HD, d = o % HD;
            dst[(((size_t)b_ * NH + h) * NN + n) * HD + d] = acc[i][j] + bias[o];
        }
    }
}

// =====================  Flash attention  =====================
// One block per (b, h, 64-row Q tile). Online softmax over 32 KV tiles of 64.
#define SPAD 65

__global__ __launch_bounds__(256) void attn_kernel(float* __restrict__ out)
{
    extern __shared__ float sm[];
    float* Qs = sm;                 // [64][65]
    float* Ks = Qs + 64 * SPAD;     // [64][65]  (rows = kv pos, cols = d)
    float* Vs = Ks + 64 * SPAD;     // [64][65]
    float* Ps = Vs + 64 * SPAD;     // [64][65]

    const int b = blockIdx.z, h = blockIdx.y;
    const int q0 = blockIdx.x * 64;
    const size_t hb = ((size_t)b * NH + h) * NN;
    const float* qbase = g_q + hb * HD;
    const float* kbase = g_k + hb * HD;
    const float* vbase = g_v + hb * HD;

    const int tid = threadIdx.x;
    const int ty = tid >> 4, tx = tid & 15;

    // Load Q tile (64x64, 16 elems/thread, coalesced)
#pragma unroll
    for (int p = 0; p < 16; p++) {
        int e = tid + p * 256;
        int r = e >> 6, c = e & 63;
        Qs[r * SPAD + c] = qbase[(size_t)(q0 + r) * HD + c];
    }

    float o_acc[4][4];
    float mrow[4], lrow[4];
#pragma unroll
    for (int i = 0; i < 4; i++) {
        mrow[i] = -INFINITY; lrow[i] = 0.f;
#pragma unroll
        for (int j = 0; j < 4; j++) o_acc[i][j] = 0.f;
    }

    for (int j0 = 0; j0 < NN; j0 += 64) {
        __syncthreads();   // protect Ks/Vs/Ps from prior iter readers
#pragma unroll
        for (int p = 0; p < 16; p++) {
            int e = tid + p * 256;
            int r = e >> 6, c = e & 63;
            Ks[r * SPAD + c] = kbase[(size_t)(j0 + r) * HD + c];
            Vs[r * SPAD + c] = vbase[(size_t)(j0 + r) * HD + c];
        }
        __syncthreads();

        // S = scale * Q @ K^T   (4x4 per thread)
        float s[4][4];
#pragma unroll
        for (int i = 0; i < 4; i++)
#pragma unroll
            for (int j = 0; j < 4; j++) s[i][j] = 0.f;

#pragma unroll 8
        for (int kk = 0; kk < 64; kk++) {
            float a[4], bv[4];
#pragma unroll
            for (int i = 0; i < 4; i++) a[i]  = Qs[(4 * ty + i) * SPAD + kk];
#pragma unroll
            for (int j = 0; j < 4; j++) bv[j] = Ks[(4 * tx + j) * SPAD + kk];
#pragma unroll
            for (int i = 0; i < 4; i++)
#pragma unroll
                for (int j = 0; j < 4; j++)
                    s[i][j] = fmaf(a[i], bv[j], s[i][j]);
        }

        // online softmax per row (reduce across the 16 tx lanes)
#pragma unroll
        for (int i = 0; i < 4; i++) {
            float mloc = -INFINITY;
#pragma unroll
            for (int j = 0; j < 4; j++) {
                s[i][j] *= 0.125f;   // HEAD_DIM^-0.5
                mloc = fmaxf(mloc, s[i][j]);
            }
#pragma unroll
            for (int off = 8; off >= 1; off >>= 1)
                mloc = fmaxf(mloc, __shfl_xor_sync(0xffffffffu, mloc, off));
            float mnew = fmaxf(mrow[i], mloc);
            float alpha = __expf(mrow[i] - mnew);   // 0 on first tile (-inf - finite)
            float rsum = 0.f;
#pragma unroll
            for (int j = 0; j < 4; j++) {
                s[i][j] = __expf(s[i][j] - mnew);
                rsum += s[i][j];
            }
#pragma unroll
            for (int off = 8; off >= 1; off >>= 1)
                rsum += __shfl_xor_sync(0xffffffffu, rsum, off);
            lrow[i] = lrow[i] * alpha + rsum;
            mrow[i] = mnew;
#pragma unroll
            for (int j = 0; j < 4; j++) {
                o_acc[i][j] *= alpha;
                Ps[(4 * ty + i) * SPAD + 4 * tx + j] = s[i][j];
            }
        }
        __syncthreads();

        // O += P @ V
#pragma unroll 8
        for (int k = 0; k < 64; k++) {
            float a[4], bv[4];
#pragma unroll
            for (int i = 0; i < 4; i++) a[i]  = Ps[(4 * ty + i) * SPAD + k];
#pragma unroll
            for (int j = 0; j < 4; j++) bv[j] = Vs[k * SPAD + 4 * tx + j];
#pragma unroll
            for (int i = 0; i < 4; i++)
#pragma unroll
                for (int j = 0; j < 4; j++)
                    o_acc[i][j] = fmaf(a[i], bv[j], o_acc[i][j]);
        }
    }

    // Normalize and write, concat-head layout [B,N,DIM]
#pragma unroll
    for (int i = 0; i < 4; i++) {
        float inv = 1.f / lrow[i];
        int n = q0 + 4 * ty + i;
#pragma unroll
        for (int j = 0; j < 4; j++) {
            out[((size_t)b * NN + n) * DIM + h * HD + 4 * tx + j] = o_acc[i][j] * inv;
        }
    }
}

extern "C" void kernel_launch(void* const* d_in, const int* in_sizes, int n_in,
                              void* d_out, int out_size)
{
    (void)in_sizes; (void)n_in; (void)out_size;
    const float* x  = (const float*)d_in[0];
    const float* wq = (const float*)d_in[1];
    const float* bq = (const float*)d_in[2];
    const float* wk = (const float*)d_in[3];
    const float* bk = (const float*)d_in[4];
    const float* wv = (const float*)d_in[5];
    const float* bv = (const float*)d_in[6];
    float* out = (float*)d_out;

    // QKV projections: grid (768/128, 8192/128, 3)
    dim3 g1(DIM / Bb_N, MROWS / Bb_M, 3);
    qkv_kernel<<<g1, 256>>>(x, wq, bq, wk, bk, wv, bv);

    // Flash attention: grid (2048/64 q-tiles, 12 heads, 4 batch)
    size_t smem = 4 * 64 * SPAD * sizeof(float);   // 66,560 B
    cudaFuncSetAttribute(attn_kernel, cudaFuncAttributeMaxDynamicSharedMemorySize,
                         (int)smem);
    dim3 g2(NN / 64, NH, BB);
    attn_kernel<<<g2, 256, smem>>>(out);
}

// round 4
// speedup vs baseline: 1.1101x; 1.1101x over previous
#include <cuda_runtime.h>
#include <math.h>

#define BB 4
#define NN 2048
#define DIM 768
#define NH 12
#define HD 64
#define MROWS (BB*NN)   // 8192

// Scratch: q,k,v in [b,h,n,d] layout (25.2 MB each)
__device__ float g_q[BB*NH*NN*HD];
__device__ float g_k[BB*NH*NN*HD];
__device__ float g_v[BB*NH*NN*HD];

// =====================  QKV projection GEMM  =====================
#define Bb_M 128
#define Bb_N 128
#define KC   16
#define XPAD 132

__global__ __launch_bounds__(256) void qkv_kernel(
    const float* __restrict__ x,
    const float* __restrict__ wq, const float* __restrict__ bq,
    const float* __restrict__ wk, const float* __restrict__ bk,
    const float* __restrict__ wv, const float* __restrict__ bv)
{
    __shared__ float Xs[KC][XPAD];
    __shared__ float Ws[KC][XPAD];

    const int mat = blockIdx.z;
    const float* w    = (mat == 0) ? wq : (mat == 1) ? wk : wv;
    const float* bias = (mat == 0) ? bq : (mat == 1) ? bk : bv;
    float* dst        = (mat == 0) ? g_q : (mat == 1) ? g_k : g_v;

    const int m0 = blockIdx.y * Bb_M;
    const int o0 = blockIdx.x * Bb_N;
    const int tid = threadIdx.x;
    const int ty = tid >> 4, tx = tid & 15;

    float acc[8][8];
#pragma unroll
    for (int i = 0; i < 8; i++)
#pragma unroll
        for (int j = 0; j < 8; j++) acc[i][j] = 0.f;

    for (int kb = 0; kb < DIM; kb += KC) {
        __syncthreads();
#pragma unroll
        for (int p = 0; p < 2; p++) {
            int idx = tid + p * 256;
            int row = idx >> 2;
            int k4  = idx & 3;
            float4 xv  = *(const float4*)(x + (size_t)(m0 + row) * DIM + kb + 4 * k4);
            float4 wv4 = *(const float4*)(w + (size_t)(o0 + row) * DIM + kb + 4 * k4);
            Xs[4*k4+0][row] = xv.x;  Xs[4*k4+1][row] = xv.y;
            Xs[4*k4+2][row] = xv.z;  Xs[4*k4+3][row] = xv.w;
            Ws[4*k4+0][row] = wv4.x; Ws[4*k4+1][row] = wv4.y;
            Ws[4*k4+2][row] = wv4.z; Ws[4*k4+3][row] = wv4.w;
        }
        __syncthreads();
#pragma unroll
        for (int kk = 0; kk < KC; kk++) {
            float a[8], bv8[8];
            *(float4*)(a)      = *(const float4*)&Xs[kk][8*ty];
            *(float4*)(a + 4)  = *(const float4*)&Xs[kk][8*ty + 4];
            *(float4*)(bv8)    = *(const float4*)&Ws[kk][8*tx];
            *(float4*)(bv8 + 4)= *(const float4*)&Ws[kk][8*tx + 4];
#pragma unroll
            for (int i = 0; i < 8; i++)
#pragma unroll
                for (int j = 0; j < 8; j++)
                    acc[i][j] = fmaf(a[i], bv8[j], acc[i][j]);
        }
    }

#pragma unroll
    for (int i = 0; i < 8; i++) {
        int m = m0 + 8 * ty + i;
        int b_ = m / NN, n = m % NN;
#pragma unroll
        for (int j = 0; j < 8; j++) {
            int o = o0 + 8 * tx + j;
            int h = o / HD, d = o % HD;
            dst[(((size_t)b_ * NH + h) * NN + n) * HD + d] = acc[i][j] + bias[o];
        }
    }
}

// =====================  Flash attention v2  =====================
// 128-row Q tile, 64-col KV tile. 256 threads, 8x4 micro-tile.
// All inner-loop smem reads are float4 (d-major / kv-major layouts).
#define QT 128
#define KT 64
#define QP 132   // 128 + 4 pad (16B-aligned rows)
#define KP 68    // 64 + 4 pad

__global__ __launch_bounds__(256) void attn_kernel(float* __restrict__ out)
{
    extern __shared__ float sm[];
    float* Qt = sm;                 // [64][QP]  d-major:  Qt[d][qrow]
    float* Kt = Qt + 64 * QP;       // [64][KP]  d-major:  Kt[d][kv]
    float* Vs = Kt + 64 * KP;       // [64][KP]  kv-major: Vs[kv][d]
    float* Pt = Vs + 64 * KP;       // [64][QP]  kv-major: Pt[kv][qrow]

    const int b = blockIdx.z, h = blockIdx.y;
    const int q0 = blockIdx.x * QT;
    const size_t hb = ((size_t)b * NH + h) * NN;
    const float* qbase = g_q + hb * HD;
    const float* kbase = g_k + hb * HD;
    const float* vbase = g_v + hb * HD;

    const int tid = threadIdx.x;
    const int ty = tid >> 4, tx = tid & 15;   // rows 8*ty.., cols 4*tx..

    // Load Q tile transposed: 128x64 = 2048 float4, 8 per thread
#pragma unroll
    for (int p = 0; p < 8; p++) {
        int e = tid + p * 256;
        int row = e >> 4, d4 = e & 15;
        float4 v = *(const float4*)(qbase + (size_t)(q0 + row) * HD + 4 * d4);
        Qt[(4*d4+0) * QP + row] = v.x;
        Qt[(4*d4+1) * QP + row] = v.y;
        Qt[(4*d4+2) * QP + row] = v.z;
        Qt[(4*d4+3) * QP + row] = v.w;
    }

    float o_acc[8][4];
    float mrow[8], lrow[8];
#pragma unroll
    for (int i = 0; i < 8; i++) {
        mrow[i] = -INFINITY; lrow[i] = 0.f;
#pragma unroll
        for (int j = 0; j < 4; j++) o_acc[i][j] = 0.f;
    }

    for (int j0 = 0; j0 < NN; j0 += KT) {
        __syncthreads();   // protect Kt/Vs/Pt from prior-iter readers
        // K transposed (4 float4/thread), V direct (4 float4/thread)
#pragma unroll
        for (int p = 0; p < 4; p++) {
            int e = tid + p * 256;
            int kv = e >> 4, d4 = e & 15;
            float4 kvec = *(const float4*)(kbase + (size_t)(j0 + kv) * HD + 4 * d4);
            Kt[(4*d4+0) * KP + kv] = kvec.x;
            Kt[(4*d4+1) * KP + kv] = kvec.y;
            Kt[(4*d4+2) * KP + kv] = kvec.z;
            Kt[(4*d4+3) * KP + kv] = kvec.w;
            float4 vvec = *(const float4*)(vbase + (size_t)(j0 + kv) * HD + 4 * d4);
            *(float4*)&Vs[kv * KP + 4 * d4] = vvec;
        }
        __syncthreads();

        // S = scale * Q @ K^T  — 3x LDS.128 per 32 FMA
        float s[8][4];
#pragma unroll
        for (int i = 0; i < 8; i++)
#pragma unroll
            for (int j = 0; j < 4; j++) s[i][j] = 0.f;

#pragma unroll 4
        for (int kk = 0; kk < 64; kk++) {
            float a[8], bv4[4];
            *(float4*)(a)     = *(const float4*)&Qt[kk * QP + 8 * ty];
            *(float4*)(a + 4) = *(const float4*)&Qt[kk * QP + 8 * ty + 4];
            *(float4*)(bv4)   = *(const float4*)&Kt[kk * KP + 4 * tx];
#pragma unroll
            for (int i = 0; i < 8; i++)
#pragma unroll
                for (int j = 0; j < 4; j++)
                    s[i][j] = fmaf(a[i], bv4[j], s[i][j]);
        }

        // online softmax per row (reduce over 16 tx lanes)
#pragma unroll
        for (int i = 0; i < 8; i++) {
            float mloc = -INFINITY;
#pragma unroll
            for (int j = 0; j < 4; j++) {
                s[i][j] *= 0.125f;
                mloc = fmaxf(mloc, s[i][j]);
            }
#pragma unroll
            for (int off = 8; off >= 1; off >>= 1)
                mloc = fmaxf(mloc, __shfl_xor_sync(0xffffffffu, mloc, off));
            float mnew = fmaxf(mrow[i], mloc);
            float alpha = __expf(mrow[i] - mnew);
            float rsum = 0.f;
#pragma unroll
            for (int j = 0; j < 4; j++) {
                s[i][j] = __expf(s[i][j] - mnew);
                rsum += s[i][j];
            }
#pragma unroll
            for (int off = 8; off >= 1; off >>= 1)
                rsum += __shfl_xor_sync(0xffffffffu, rsum, off);
            lrow[i] = lrow[i] * alpha + rsum;
            mrow[i] = mnew;
#pragma unroll
            for (int j = 0; j < 4; j++) o_acc[i][j] *= alpha;
        }

        // Store P transposed: Pt[kv][qrow], float4 along qrow
#pragma unroll
        for (int j = 0; j < 4; j++) {
            float4 v0 = make_float4(s[0][j], s[1][j], s[2][j], s[3][j]);
            float4 v1 = make_float4(s[4][j], s[5][j], s[6][j], s[7][j]);
            float* p = &Pt[(4 * tx + j) * QP + 8 * ty];
            *(float4*)(p)     = v0;
            *(float4*)(p + 4) = v1;
        }
        __syncthreads();

        // O += P @ V  — 3x LDS.128 per 32 FMA
#pragma unroll 4
        for (int k = 0; k < 64; k++) {
            float a[8], bv4[4];
            *(float4*)(a)     = *(const float4*)&Pt[k * QP + 8 * ty];
            *(float4*)(a + 4) = *(const float4*)&Pt[k * QP + 8 * ty + 4];
            *(float4*)(bv4)   = *(const float4*)&Vs[k * KP + 4 * tx];
#pragma unroll
            for (int i = 0; i < 8; i++)
#pragma unroll
                for (int j = 0; j < 4; j++)
                    o_acc[i][j] = fmaf(a[i], bv4[j], o_acc[i][j]);
        }
    }

    // Normalize and write, concat-head layout [B,N,DIM], float4 stores
#pragma unroll
    for (int i = 0; i < 8; i++) {
        float inv = 1.f / lrow[i];
        int n = q0 + 8 * ty + i;
        float4 o4 = make_float4(o_acc[i][0] * inv, o_acc[i][1] * inv,
                                o_acc[i][2] * inv, o_acc[i][3] * inv);
        *(float4*)&out[((size_t)b * NN + n) * DIM + h * HD + 4 * tx] = o4;
    }
}

extern "C" void kernel_launch(void* const* d_in, const int* in_sizes, int n_in,
                              void* d_out, int out_size)
{
    (void)in_sizes; (void)n_in; (void)out_size;
    const float* x  = (const float*)d_in[0];
    const float* wq = (const float*)d_in[1];
    const float* bq = (const float*)d_in[2];
    const float* wk = (const float*)d_in[3];
    const float* bk = (const float*)d_in[4];
    const float* wv = (const float*)d_in[5];
    const float* bv = (const float*)d_in[6];
    float* out = (float*)d_out;

    dim3 g1(DIM / Bb_N, MROWS / Bb_M, 3);
    qkv_kernel<<<g1, 256>>>(x, wq, bq, wk, bk, wv, bv);

    size_t smem = (size_t)(64 * QP * 2 + 64 * KP * 2) * sizeof(float);  // 102400 B
    cudaFuncSetAttribute(attn_kernel, cudaFuncAttributeMaxDynamicSharedMemorySize,
                         (int)smem);
    dim3 g2(NN / QT, NH, BB);
    attn_kernel<<<g2, 256, smem>>>(out);
}